// round 10
// baseline (speedup 1.0000x reference)
#include <cuda_runtime.h>
#include <math.h>

#define NTOT    16384
#define TLEN    41
#define NSTEP   40
#define THREADS 256
#define PPB     128          // particles per block; 4 particles per thread
#define BLOCKS  128

// ---- smem float offsets ----
#define OFF_WIN  0            // [24k][80j]
#define OFF_BIN  1920         // [80]
#define OFF_WH   2000         // [4l][80k][80j]
#define OFF_BH   27600        // [4][80]
#define OFF_WOUT 27920        // [80k][20j]
#define OFF_BOUT 29520        // [20]
#define OFF_U    29540        // [40][4]
#define OFF_Y    29700        // [20][128] particle state
#define OFF_FQ   32260        // [8][128] fq partials
#define OFF_A    33284        // [80][128] activations A
#define OFF_B    43524        // [80][128] activations B / output partials
#define SMEM_FLOATS 53764     // 215,056 B

typedef unsigned long long u64;

#define FMA2(d, a, b, c) \
    asm("fma.rn.f32x2 %0, %1, %2, %3;" : "=l"(d) : "l"(a), "l"(b), "l"(c))
#define PACK2(d, f) do { unsigned int _u = __float_as_uint(f); \
    asm("mov.b64 %0, {%1, %2};" : "=l"(d) : "r"(_u), "r"(_u)); } while (0)
#define UNPACK2(lo, hi, s) do { unsigned int _a, _b; \
    asm("mov.b64 {%0, %1}, %2;" : "=r"(_a), "=r"(_b) : "l"(s)); \
    lo = __uint_as_float(_a); hi = __uint_as_float(_b); } while (0)
#define TANHA(d, x) asm("tanh.approx.f32 %0, %1;" : "=f"(d) : "f"(x))

extern __shared__ float smem[];

// 4-particle FMA2 bundle over 5 ulonglong2 weight vectors
#define FMA_BLOCK(ACC, WPTR, X0, X1, X2, X3)                                   \
    do {                                                                       \
        const ulonglong2* _w = (const ulonglong2*)(WPTR);                      \
        _Pragma("unroll")                                                      \
        for (int _q = 0; _q < 5; _q++) {                                       \
            ulonglong2 _wv = _w[_q];                                           \
            FMA2(ACC[0][2*_q], _wv.x, X0, ACC[0][2*_q]);                       \
            FMA2(ACC[0][2*_q+1], _wv.y, X0, ACC[0][2*_q+1]);                   \
            FMA2(ACC[1][2*_q], _wv.x, X1, ACC[1][2*_q]);                       \
            FMA2(ACC[1][2*_q+1], _wv.y, X1, ACC[1][2*_q+1]);                   \
            FMA2(ACC[2][2*_q], _wv.x, X2, ACC[2][2*_q]);                       \
            FMA2(ACC[2][2*_q+1], _wv.y, X2, ACC[2][2*_q+1]);                   \
            FMA2(ACC[3][2*_q], _wv.x, X3, ACC[3][2*_q]);                       \
            FMA2(ACC[3][2*_q+1], _wv.y, X3, ACC[3][2*_q+1]);                   \
        }                                                                      \
    } while (0)

__global__ void __launch_bounds__(THREADS, 1)
sde_kernel(const float* __restrict__ z, const float* __restrict__ t,
           const float* __restrict__ Tx, const float* __restrict__ noise,
           const float* __restrict__ tw_in, const float* __restrict__ tb_in,
           const float* __restrict__ tw_h,  const float* __restrict__ tb_h,
           const float* __restrict__ tw_out,const float* __restrict__ tb_out,
           const float* __restrict__ dw_in, const float* __restrict__ db_in,
           const float* __restrict__ dw_h,  const float* __restrict__ db_h,
           const float* __restrict__ dw_out,const float* __restrict__ db_out,
           float* __restrict__ ys, float* __restrict__ lqout) {
    float* s_win  = smem + OFF_WIN;
    float* s_bin  = smem + OFF_BIN;
    float* s_wh   = smem + OFF_WH;
    float* s_bh   = smem + OFF_BH;
    float* s_wout = smem + OFF_WOUT;
    float* s_bout = smem + OFF_BOUT;
    float* s_u    = smem + OFF_U;
    float* s_y    = smem + OFF_Y;
    float* s_fq   = smem + OFF_FQ;
    float* s_A    = smem + OFF_A;
    float* s_B    = smem + OFF_B;

    const int tid  = threadIdx.x;
    const int w    = tid >> 5;      // warp 0..7
    const int jg   = w >> 1;        // j-group 0..3 (pair id)
    const int h    = w & 1;         // k-half within the pair
    const int oh   = 1 - h;
    const int quad = tid & 31;      // particle quad 0..31
    const int col0 = 4 * quad;      // smem column of particle 0 (16B aligned)
    const int jb   = 20 * jg;       // j-slice [jb, jb+20)

    // ---- cooperative load + transpose of drift weights into smem ----
    for (int idx = tid; idx < 24 * 80; idx += THREADS) {
        int j = idx / 24, k = idx % 24;
        s_win[k * 80 + j] = dw_in[idx];
    }
    for (int idx = tid; idx < 4 * 6400; idx += THREADS) {
        int l = idx / 6400, r = idx % 6400, j = r / 80, k = r % 80;
        s_wh[l * 6400 + k * 80 + j] = dw_h[idx];
    }
    for (int idx = tid; idx < 20 * 80; idx += THREADS) {
        int j = idx / 80, k = idx % 80;
        s_wout[k * 20 + j] = dw_out[idx];
    }
    for (int idx = tid; idx < 80;  idx += THREADS) s_bin[idx]  = db_in[idx];
    for (int idx = tid; idx < 320; idx += THREADS) s_bh[idx]   = db_h[idx];
    for (int idx = tid; idx < 20;  idx += THREADS) s_bout[idx] = db_out[idx];

    // ---- t-MLP fused: threads [0,40) compute u(t_i) -> s_u ----
    if (tid < NSTEP) {
        float ti = t[tid];
        float hh[20], h2[20];
#pragma unroll
        for (int j = 0; j < 20; j++) hh[j] = fmaxf(tw_in[j] * ti + tb_in[j], 0.f);
        for (int l = 0; l < 4; l++) {
            const float* ww = tw_h + l * 400;
            const float* bb = tb_h + l * 20;
#pragma unroll
            for (int j = 0; j < 20; j++) {
                float a = bb[j];
#pragma unroll
                for (int k = 0; k < 20; k++) a += ww[j * 20 + k] * hh[k];
                h2[j] = fmaxf(a, 0.f);
            }
#pragma unroll
            for (int j = 0; j < 20; j++) hh[j] = h2[j];
        }
#pragma unroll
        for (int c = 0; c < 4; c++) {
            float a = tb_out[c];
#pragma unroll
            for (int k = 0; k < 20; k++) a += tw_out[c * 20 + k] * hh[k];
            s_u[tid * 4 + c] = a;
        }
    }

    const int n0 = blockIdx.x * PPB + col0;   // particles n0..n0+3
    const float Tval = Tx[n0 >> 6];           // same for all 4 (col0 % 4 == 0)
    const float dt  = t[1] - t[0];
    const float sdt = sqrtf(dt);

    // ---- init: dims strided by warp (d = w, w+8, w+16) ----
    for (int d = w; d < 20; d += 8) {
        float v0 = z[(size_t)(n0 + 0) * 20 + d];
        float v1 = z[(size_t)(n0 + 1) * 20 + d];
        float v2 = z[(size_t)(n0 + 2) * 20 + d];
        float v3 = z[(size_t)(n0 + 3) * 20 + d];
        *(float4*)(s_y + d * 128 + col0) = make_float4(v0, v1, v2, v3);
        ys[(size_t)(n0 + 0) * 20 + d] = v0;
        ys[(size_t)(n0 + 1) * 20 + d] = v1;
        ys[(size_t)(n0 + 2) * 20 + d] = v2;
        ys[(size_t)(n0 + 3) * 20 + d] = v3;
    }
    float lq[4] = {0.f, 0.f, 0.f, 0.f};
    if (w == 0) {
#pragma unroll
        for (int p = 0; p < 4; p++) {
            int np = n0 + p;
            if (np >= 40 && (np - 40) % 41 == 0) lqout[(np - 40) / 41] = 0.f;
        }
    }
    __syncthreads();

    for (int step = 0; step < NSTEP; step++) {
        float ut[4];
#pragma unroll
        for (int c = 0; c < 4; c++) ut[c] = s_u[step * 4 + c] * Tval;

        // ======== input layer: pair (jg,h) splits k; j in [jb,jb+20) ======
        {
            u64 acc[4][10];
            if (h == 0) {
                const ulonglong2* bv = (const ulonglong2*)(s_bin + jb);
#pragma unroll
                for (int q5 = 0; q5 < 5; q5++) {
                    ulonglong2 b = bv[q5];
#pragma unroll
                    for (int p = 0; p < 4; p++) { acc[p][2*q5] = b.x; acc[p][2*q5+1] = b.y; }
                }
#pragma unroll 2
                for (int k = 0; k < 12; k++) {
                    float4 yk = *(const float4*)(s_y + k * 128 + col0);
                    u64 x0, x1, x2, x3;
                    PACK2(x0, yk.x); PACK2(x1, yk.y); PACK2(x2, yk.z); PACK2(x3, yk.w);
                    FMA_BLOCK(acc, s_win + k * 80 + jb, x0, x1, x2, x3);
                }
            } else {
#pragma unroll
                for (int p = 0; p < 4; p++)
#pragma unroll
                    for (int q = 0; q < 10; q++) acc[p][q] = 0ull;
#pragma unroll 2
                for (int k = 12; k < 20; k++) {
                    float4 yk = *(const float4*)(s_y + k * 128 + col0);
                    u64 x0, x1, x2, x3;
                    PACK2(x0, yk.x); PACK2(x1, yk.y); PACK2(x2, yk.z); PACK2(x3, yk.w);
                    FMA_BLOCK(acc, s_win + k * 80 + jb, x0, x1, x2, x3);
                }
#pragma unroll
                for (int c = 0; c < 4; c++) {
                    u64 xu; PACK2(xu, ut[c]);
                    FMA_BLOCK(acc, s_win + (20 + c) * 80 + jb, xu, xu, xu, xu);
                }
            }
            // write the j-half the PARTNER combines
            {
                float* pw = s_A + (jb + 10 * oh) * 128 + col0;
#pragma unroll
                for (int qi = 0; qi < 5; qi++) {
                    int q = 5 * oh + qi;
                    float a0,b0,a1,b1,a2,b2,a3,b3;
                    UNPACK2(a0,b0,acc[0][q]); UNPACK2(a1,b1,acc[1][q]);
                    UNPACK2(a2,b2,acc[2][q]); UNPACK2(a3,b3,acc[3][q]);
                    *(float4*)(pw + (2*qi)   * 128) = make_float4(a0,a1,a2,a3);
                    *(float4*)(pw + (2*qi+1) * 128) = make_float4(b0,b1,b2,b3);
                }
            }
            __syncthreads();
            // combine own half: partner's partial + own regs, relu
            {
                float* cw = s_A + (jb + 10 * h) * 128 + col0;
#pragma unroll
                for (int qi = 0; qi < 5; qi++) {
                    int q = 5 * h + qi;
                    float4 r0 = *(const float4*)(cw + (2*qi)   * 128);
                    float4 r1 = *(const float4*)(cw + (2*qi+1) * 128);
                    float a0,b0,a1,b1,a2,b2,a3,b3;
                    UNPACK2(a0,b0,acc[0][q]); UNPACK2(a1,b1,acc[1][q]);
                    UNPACK2(a2,b2,acc[2][q]); UNPACK2(a3,b3,acc[3][q]);
                    a0 += r0.x; a1 += r0.y; a2 += r0.z; a3 += r0.w;
                    b0 += r1.x; b1 += r1.y; b2 += r1.z; b3 += r1.w;
                    *(float4*)(cw + (2*qi)   * 128) =
                        make_float4(fmaxf(a0,0.f), fmaxf(a1,0.f), fmaxf(a2,0.f), fmaxf(a3,0.f));
                    *(float4*)(cw + (2*qi+1) * 128) =
                        make_float4(fmaxf(b0,0.f), fmaxf(b1,0.f), fmaxf(b2,0.f), fmaxf(b3,0.f));
                }
            }
        }
        __syncthreads();

        // ======== 4 hidden layers 80 -> 80: pair k-split, tanh ========
        float* hin  = s_A;
        float* hout = s_B;
        for (int l = 0; l < 4; l++) {
            u64 acc[4][10];
            if (h == 0) {
                const ulonglong2* bv = (const ulonglong2*)(s_bh + l * 80 + jb);
#pragma unroll
                for (int q5 = 0; q5 < 5; q5++) {
                    ulonglong2 b = bv[q5];
#pragma unroll
                    for (int p = 0; p < 4; p++) { acc[p][2*q5] = b.x; acc[p][2*q5+1] = b.y; }
                }
            } else {
#pragma unroll
                for (int p = 0; p < 4; p++)
#pragma unroll
                    for (int q = 0; q < 10; q++) acc[p][q] = 0ull;
            }
            const float* wrow = s_wh + l * 6400 + (40 * h) * 80 + jb;
            const float* arow = hin + (40 * h) * 128 + col0;
#pragma unroll 2
            for (int kk = 0; kk < 40; kk++) {
                float4 hk = *(const float4*)(arow + kk * 128);
                u64 x0, x1, x2, x3;
                PACK2(x0, hk.x); PACK2(x1, hk.y); PACK2(x2, hk.z); PACK2(x3, hk.w);
                FMA_BLOCK(acc, wrow + kk * 80, x0, x1, x2, x3);
            }
            // write partner's half
            {
                float* pw = hout + (jb + 10 * oh) * 128 + col0;
#pragma unroll
                for (int qi = 0; qi < 5; qi++) {
                    int q = 5 * oh + qi;
                    float a0,b0,a1,b1,a2,b2,a3,b3;
                    UNPACK2(a0,b0,acc[0][q]); UNPACK2(a1,b1,acc[1][q]);
                    UNPACK2(a2,b2,acc[2][q]); UNPACK2(a3,b3,acc[3][q]);
                    *(float4*)(pw + (2*qi)   * 128) = make_float4(a0,a1,a2,a3);
                    *(float4*)(pw + (2*qi+1) * 128) = make_float4(b0,b1,b2,b3);
                }
            }
            __syncthreads();
            // combine own half + tanh
            {
                float* cw = hout + (jb + 10 * h) * 128 + col0;
#pragma unroll
                for (int qi = 0; qi < 5; qi++) {
                    int q = 5 * h + qi;
                    float4 r0 = *(const float4*)(cw + (2*qi)   * 128);
                    float4 r1 = *(const float4*)(cw + (2*qi+1) * 128);
                    float a0,b0,a1,b1,a2,b2,a3,b3;
                    UNPACK2(a0,b0,acc[0][q]); UNPACK2(a1,b1,acc[1][q]);
                    UNPACK2(a2,b2,acc[2][q]); UNPACK2(a3,b3,acc[3][q]);
                    a0 += r0.x; a1 += r0.y; a2 += r0.z; a3 += r0.w;
                    b0 += r1.x; b1 += r1.y; b2 += r1.z; b3 += r1.w;
                    TANHA(a0,a0); TANHA(a1,a1); TANHA(a2,a2); TANHA(a3,a3);
                    TANHA(b0,b0); TANHA(b1,b1); TANHA(b2,b2); TANHA(b3,b3);
                    *(float4*)(cw + (2*qi)   * 128) = make_float4(a0,a1,a2,a3);
                    *(float4*)(cw + (2*qi+1) * 128) = make_float4(b0,b1,b2,b3);
                }
            }
            __syncthreads();
            float* tmp = hin; hin = hout; hout = tmp;
        }
        // after 4 swaps: hin == s_A (final hidden), hout == s_B (free)

        // ---- prefetch noise for own strided dims (hidden under output) ----
        float nz[3][4];
        {
            int di = 0;
            for (int d = w; d < 20; d += 8, di++) {
#pragma unroll
                for (int p = 0; p < 4; p++)
                    nz[di][p] = noise[((size_t)step * NTOT + n0 + p) * 22 + d];
            }
        }

        // ======== output layer: warp (jg,h) k in [20jg+10h,+10), 20 j =====
        {
            u64 oc[4][10];
#pragma unroll
            for (int p = 0; p < 4; p++)
#pragma unroll
                for (int q = 0; q < 10; q++) oc[p][q] = 0ull;
            const int kb = 20 * jg + 10 * h;
            const float* hr = hin + kb * 128 + col0;
            const float* wr = s_wout + kb * 20;
#pragma unroll 2
            for (int kk = 0; kk < 10; kk++) {
                float4 hk = *(const float4*)(hr + kk * 128);
                u64 x0, x1, x2, x3;
                PACK2(x0, hk.x); PACK2(x1, hk.y); PACK2(x2, hk.z); PACK2(x3, hk.w);
                FMA_BLOCK(oc, wr + kk * 20, x0, x1, x2, x3);
            }
            // pair-combine into s_B rows [20jg, +20) (no activation)
            {
                float* pw = hout + (20 * jg + 10 * oh) * 128 + col0;
#pragma unroll
                for (int qi = 0; qi < 5; qi++) {
                    int q = 5 * oh + qi;
                    float a0,b0,a1,b1,a2,b2,a3,b3;
                    UNPACK2(a0,b0,oc[0][q]); UNPACK2(a1,b1,oc[1][q]);
                    UNPACK2(a2,b2,oc[2][q]); UNPACK2(a3,b3,oc[3][q]);
                    *(float4*)(pw + (2*qi)   * 128) = make_float4(a0,a1,a2,a3);
                    *(float4*)(pw + (2*qi+1) * 128) = make_float4(b0,b1,b2,b3);
                }
            }
            __syncthreads();
            {
                float* cw = hout + (20 * jg + 10 * h) * 128 + col0;
#pragma unroll
                for (int qi = 0; qi < 5; qi++) {
                    int q = 5 * h + qi;
                    float4 r0 = *(const float4*)(cw + (2*qi)   * 128);
                    float4 r1 = *(const float4*)(cw + (2*qi+1) * 128);
                    float a0,b0,a1,b1,a2,b2,a3,b3;
                    UNPACK2(a0,b0,oc[0][q]); UNPACK2(a1,b1,oc[1][q]);
                    UNPACK2(a2,b2,oc[2][q]); UNPACK2(a3,b3,oc[3][q]);
                    a0 += r0.x; a1 += r0.y; a2 += r0.z; a3 += r0.w;
                    b0 += r1.x; b1 += r1.y; b2 += r1.z; b3 += r1.w;
                    *(float4*)(cw + (2*qi)   * 128) = make_float4(a0,a1,a2,a3);
                    *(float4*)(cw + (2*qi+1) * 128) = make_float4(b0,b1,b2,b3);
                }
            }
        }
        __syncthreads();

        // ======== reduce over 4 k-groups + SDE update (strided dims) ======
        // h = -y ; f = o + y ; uu = 2(o + 2y) ; f_logqp = 2*sum((o+2y)^2)
        {
            float fq[4] = {0.f, 0.f, 0.f, 0.f};
            int di = 0;
            for (int d = w; d < 20; d += 8, di++) {
                float4 yv = *(const float4*)(s_y + d * 128 + col0);
                float bo = s_bout[d];
                float s0 = bo, s1 = bo, s2 = bo, s3 = bo;
#pragma unroll
                for (int g = 0; g < 4; g++) {
                    float4 p = *(const float4*)(s_B + (g * 20 + d) * 128 + col0);
                    s0 += p.x; s1 += p.y; s2 += p.z; s3 += p.w;
                }
                float yv_[4] = {yv.x, yv.y, yv.z, yv.w};
                float sv[4] = {s0, s1, s2, s3};
                float yn[4];
#pragma unroll
                for (int p = 0; p < 4; p++) {
                    float f  = sv[p] + yv_[p];
                    float uu = sv[p] + 2.f * yv_[p];
                    fq[p] += uu * uu;
                    yn[p] = yv_[p] + f * dt + 0.5f * nz[di][p] * sdt; // SIGMA=0.5
                    ys[((size_t)(step + 1) * NTOT + n0 + p) * 20 + d] = yn[p];
                }
                *(float4*)(s_y + d * 128 + col0) = make_float4(yn[0], yn[1], yn[2], yn[3]);
            }
            *(float4*)(s_fq + w * 128 + col0) = make_float4(fq[0], fq[1], fq[2], fq[3]);
        }
        __syncthreads();

        // warp 0 owns logqp bookkeeping (s_fq stable until next step's update)
        if (w == 0) {
            float ft[4] = {0.f, 0.f, 0.f, 0.f};
#pragma unroll
            for (int g = 0; g < 8; g++) {
                float4 v = *(const float4*)(s_fq + g * 128 + col0);
                ft[0] += v.x; ft[1] += v.y; ft[2] += v.z; ft[3] += v.w;
            }
#pragma unroll
            for (int p = 0; p < 4; p++) {
                lq[p] += 2.f * ft[p] * dt;
                size_t idx = (size_t)(step + 1) * NTOT + n0 + p;
                size_t r = idx - 40;
                if (r % 41 == 0) lqout[r / 41] = lq[p];
            }
        }
    }
}

// ---------------------------------------------------------------------------
extern "C" void kernel_launch(void* const* d_in, const int* in_sizes, int n_in,
                              void* d_out, int out_size) {
    const float* z      = (const float*)d_in[0];
    const float* t      = (const float*)d_in[1];
    const float* Tx     = (const float*)d_in[2];
    const float* noise  = (const float*)d_in[3];
    const float* tw_in  = (const float*)d_in[4];
    const float* tb_in  = (const float*)d_in[5];
    const float* tw_h   = (const float*)d_in[6];
    const float* tb_h   = (const float*)d_in[7];
    const float* tw_out = (const float*)d_in[8];
    const float* tb_out = (const float*)d_in[9];
    const float* dw_in  = (const float*)d_in[10];
    const float* db_in  = (const float*)d_in[11];
    const float* dw_h   = (const float*)d_in[12];
    const float* db_h   = (const float*)d_in[13];
    const float* dw_out = (const float*)d_in[14];
    const float* db_out = (const float*)d_in[15];

    float* ys    = (float*)d_out;
    float* lqout = ys + (size_t)TLEN * NTOT * 20;

    const size_t smem_bytes = (size_t)SMEM_FLOATS * sizeof(float); // ~215 KB
    cudaFuncSetAttribute(sde_kernel, cudaFuncAttributeMaxDynamicSharedMemorySize,
                         (int)smem_bytes);

    sde_kernel<<<BLOCKS, THREADS, smem_bytes>>>(z, t, Tx, noise,
                                                tw_in, tb_in, tw_h, tb_h,
                                                tw_out, tb_out,
                                                dw_in, db_in, dw_h, db_h,
                                                dw_out, db_out, ys, lqout);
}

// round 11
// speedup vs baseline: 1.1440x; 1.1440x over previous
#include <cuda_runtime.h>
#include <math.h>

#define NTOT    16384
#define TLEN    41
#define NSTEP   40
#define THREADS 512
#define PPB     128          // particles per block; 2 particles per thread
#define BLOCKS  128

// ---- smem float offsets ----
#define OFF_WIN  0            // [24k][80j]
#define OFF_BIN  1920         // [80]
#define OFF_WH   2000         // [4l][80k][80j]
#define OFF_BH   27600        // [4][80]
#define OFF_WOUT 27920        // [80k][20j]
#define OFF_BOUT 29520        // [20]
#define OFF_U    29540        // [40][4]
#define OFF_Y    29700        // [20][128] particle state
#define OFF_FQ   32260        // [8][128] fq partials
#define OFF_A    33284        // [80][128] activations A
#define OFF_B    43524        // [80][128] activations B / output partials
#define SMEM_FLOATS 53764     // 215,056 B

typedef unsigned long long u64;

#define FMA2(d, a, b, c) \
    asm("fma.rn.f32x2 %0, %1, %2, %3;" : "=l"(d) : "l"(a), "l"(b), "l"(c))
#define PACK2(d, f) do { unsigned int _u = __float_as_uint(f); \
    asm("mov.b64 %0, {%1, %2};" : "=l"(d) : "r"(_u), "r"(_u)); } while (0)
#define UNPACK2(lo, hi, s) do { unsigned int _a, _b; \
    asm("mov.b64 {%0, %1}, %2;" : "=r"(_a), "=r"(_b) : "l"(s)); \
    lo = __uint_as_float(_a); hi = __uint_as_float(_b); } while (0)
#define TANHA(d, x) asm("tanh.approx.f32 %0, %1;" : "=f"(d) : "f"(x))
#define BARW(id) asm volatile("bar.sync %0, 64;" :: "r"(id) : "memory")

extern __shared__ float smem[];

// 2-particle FMA2 bundle over 5 ulonglong2 weight vectors
#define FMA_BLOCK(ACC, WPTR, X0, X1)                                           \
    do {                                                                       \
        const ulonglong2* _w = (const ulonglong2*)(WPTR);                      \
        _Pragma("unroll")                                                      \
        for (int _q = 0; _q < 5; _q++) {                                       \
            ulonglong2 _wv = _w[_q];                                           \
            FMA2(ACC[0][2*_q],   _wv.x, X0, ACC[0][2*_q]);                     \
            FMA2(ACC[0][2*_q+1], _wv.y, X0, ACC[0][2*_q+1]);                   \
            FMA2(ACC[1][2*_q],   _wv.x, X1, ACC[1][2*_q]);                     \
            FMA2(ACC[1][2*_q+1], _wv.y, X1, ACC[1][2*_q+1]);                   \
        }                                                                      \
    } while (0)

__global__ void __launch_bounds__(THREADS, 1)
sde_kernel(const float* __restrict__ z, const float* __restrict__ t,
           const float* __restrict__ Tx, const float* __restrict__ noise,
           const float* __restrict__ tw_in, const float* __restrict__ tb_in,
           const float* __restrict__ tw_h,  const float* __restrict__ tb_h,
           const float* __restrict__ tw_out,const float* __restrict__ tb_out,
           const float* __restrict__ dw_in, const float* __restrict__ db_in,
           const float* __restrict__ dw_h,  const float* __restrict__ db_h,
           const float* __restrict__ dw_out,const float* __restrict__ db_out,
           float* __restrict__ ys, float* __restrict__ lqout) {
    float* s_win  = smem + OFF_WIN;
    float* s_bin  = smem + OFF_BIN;
    float* s_wh   = smem + OFF_WH;
    float* s_bh   = smem + OFF_BH;
    float* s_wout = smem + OFF_WOUT;
    float* s_bout = smem + OFF_BOUT;
    float* s_u    = smem + OFF_U;
    float* s_y    = smem + OFF_Y;
    float* s_fq   = smem + OFF_FQ;
    float* s_A    = smem + OFF_A;
    float* s_B    = smem + OFF_B;

    const int tid  = threadIdx.x;
    const int w    = tid >> 5;      // warp 0..15
    const int g    = tid >> 6;      // work-group 0..7 (2 warps per group)
    const int jg   = g >> 1;        // j-group 0..3
    const int h    = g & 1;         // k-half
    const int oh   = 1 - h;
    const int pair = tid & 63;      // particle pair 0..63
    const int col0 = 2 * pair;      // smem column of particle 0
    const int jb   = 20 * jg;       // j-slice [jb, jb+20)
    // partner mini-barrier id: pairs {w, w^2} share one of 8 ids (8..15)
    const int bid  = 8 + (((w >> 2) << 1) | (w & 1));
    const int dg   = w >> 1;        // dim-group 0..7 for update phase

    // ---- cooperative load + transpose of drift weights into smem ----
    for (int idx = tid; idx < 24 * 80; idx += THREADS) {
        int j = idx / 24, k = idx % 24;
        s_win[k * 80 + j] = dw_in[idx];
    }
    for (int idx = tid; idx < 4 * 6400; idx += THREADS) {
        int l = idx / 6400, r = idx % 6400, j = r / 80, k = r % 80;
        s_wh[l * 6400 + k * 80 + j] = dw_h[idx];
    }
    for (int idx = tid; idx < 20 * 80; idx += THREADS) {
        int j = idx / 80, k = idx % 80;
        s_wout[k * 20 + j] = dw_out[idx];
    }
    for (int idx = tid; idx < 80;  idx += THREADS) s_bin[idx]  = db_in[idx];
    for (int idx = tid; idx < 320; idx += THREADS) s_bh[idx]   = db_h[idx];
    for (int idx = tid; idx < 20;  idx += THREADS) s_bout[idx] = db_out[idx];

    // ---- t-MLP fused: threads [64,104) compute u(t_i) -> s_u ----
    if (tid >= 64 && tid < 64 + NSTEP) {
        int i = tid - 64;
        float ti = t[i];
        float hh[20], h2[20];
#pragma unroll
        for (int j = 0; j < 20; j++) hh[j] = fmaxf(tw_in[j] * ti + tb_in[j], 0.f);
        for (int l = 0; l < 4; l++) {
            const float* ww = tw_h + l * 400;
            const float* bb = tb_h + l * 20;
#pragma unroll
            for (int j = 0; j < 20; j++) {
                float a = bb[j];
#pragma unroll
                for (int k = 0; k < 20; k++) a += ww[j * 20 + k] * hh[k];
                h2[j] = fmaxf(a, 0.f);
            }
#pragma unroll
            for (int j = 0; j < 20; j++) hh[j] = h2[j];
        }
#pragma unroll
        for (int c = 0; c < 4; c++) {
            float a = tb_out[c];
#pragma unroll
            for (int k = 0; k < 20; k++) a += tw_out[c * 20 + k] * hh[k];
            s_u[i * 4 + c] = a;
        }
    }

    const int n0 = blockIdx.x * PPB + col0;   // particles n0, n0+1
    const float Tval = Tx[n0 >> 6];           // same for both (n0 even)
    const float dt  = t[1] - t[0];
    const float sdt = sqrtf(dt);

    // ---- init: dims strided by dg (d = dg, dg+8, dg+16 when dg<4) ----
    for (int d = dg; d < 20; d += 8) {
        float v0 = z[(size_t)n0 * 20 + d];
        float v1 = z[(size_t)(n0 + 1) * 20 + d];
        *(float2*)(s_y + d * 128 + col0) = make_float2(v0, v1);
        ys[(size_t)n0 * 20 + d]       = v0;
        ys[(size_t)(n0 + 1) * 20 + d] = v1;
    }
    float lq0 = 0.f, lq1 = 0.f;
    if (g == 0) {   // warps 0,1 together cover all 64 pairs
        if (n0 >= 40 && (n0 - 40) % 41 == 0) lqout[(n0 - 40) / 41] = 0.f;
        int n1 = n0 + 1;
        if (n1 >= 40 && (n1 - 40) % 41 == 0) lqout[(n1 - 40) / 41] = 0.f;
    }
    __syncthreads();

    for (int step = 0; step < NSTEP; step++) {
        // ======== input layer: [y(20), ut(4)] -> j in [jb,jb+20), relu ====
        {
            u64 acc[2][10];
            if (h == 0) {
                const ulonglong2* bv = (const ulonglong2*)(s_bin + jb);
#pragma unroll
                for (int q5 = 0; q5 < 5; q5++) {
                    ulonglong2 b = bv[q5];
                    acc[0][2*q5] = b.x; acc[0][2*q5+1] = b.y;
                    acc[1][2*q5] = b.x; acc[1][2*q5+1] = b.y;
                }
#pragma unroll 2
                for (int k = 0; k < 12; k++) {
                    float2 yk = *(const float2*)(s_y + k * 128 + col0);
                    u64 x0, x1; PACK2(x0, yk.x); PACK2(x1, yk.y);
                    FMA_BLOCK(acc, s_win + k * 80 + jb, x0, x1);
                }
            } else {
#pragma unroll
                for (int p = 0; p < 2; p++)
#pragma unroll
                    for (int q = 0; q < 10; q++) acc[p][q] = 0ull;
#pragma unroll 2
                for (int k = 12; k < 20; k++) {
                    float2 yk = *(const float2*)(s_y + k * 128 + col0);
                    u64 x0, x1; PACK2(x0, yk.x); PACK2(x1, yk.y);
                    FMA_BLOCK(acc, s_win + k * 80 + jb, x0, x1);
                }
#pragma unroll
                for (int c = 0; c < 4; c++) {
                    float uv = s_u[step * 4 + c] * Tval;
                    u64 xu; PACK2(xu, uv);
                    FMA_BLOCK(acc, s_win + (20 + c) * 80 + jb, xu, xu);
                }
            }
            // write partner's j-half
            {
                float* pw = s_A + (jb + 10 * oh) * 128 + col0;
#pragma unroll
                for (int qi = 0; qi < 5; qi++) {
                    int q = 5 * oh + qi;
                    float a0, b0, a1, b1;
                    UNPACK2(a0, b0, acc[0][q]); UNPACK2(a1, b1, acc[1][q]);
                    *(float2*)(pw + (2*qi)   * 128) = make_float2(a0, a1);
                    *(float2*)(pw + (2*qi+1) * 128) = make_float2(b0, b1);
                }
            }
            BARW(bid);    // sync with partner warp (w ^ 2) only
            // combine own half: partner's partial + own regs, relu
            {
                float* cw = s_A + (jb + 10 * h) * 128 + col0;
#pragma unroll
                for (int qi = 0; qi < 5; qi++) {
                    int q = 5 * h + qi;
                    float2 r0 = *(const float2*)(cw + (2*qi)   * 128);
                    float2 r1 = *(const float2*)(cw + (2*qi+1) * 128);
                    float a0, b0, a1, b1;
                    UNPACK2(a0, b0, acc[0][q]); UNPACK2(a1, b1, acc[1][q]);
                    a0 += r0.x; a1 += r0.y; b0 += r1.x; b1 += r1.y;
                    *(float2*)(cw + (2*qi)   * 128) =
                        make_float2(fmaxf(a0, 0.f), fmaxf(a1, 0.f));
                    *(float2*)(cw + (2*qi+1) * 128) =
                        make_float2(fmaxf(b0, 0.f), fmaxf(b1, 0.f));
                }
            }
        }
        __syncthreads();

        // ======== 4 hidden layers 80 -> 80: k-half split, tanh ========
        float* hin  = s_A;
        float* hout = s_B;
        for (int l = 0; l < 4; l++) {
            u64 acc[2][10];
            if (h == 0) {
                const ulonglong2* bv = (const ulonglong2*)(s_bh + l * 80 + jb);
#pragma unroll
                for (int q5 = 0; q5 < 5; q5++) {
                    ulonglong2 b = bv[q5];
                    acc[0][2*q5] = b.x; acc[0][2*q5+1] = b.y;
                    acc[1][2*q5] = b.x; acc[1][2*q5+1] = b.y;
                }
            } else {
#pragma unroll
                for (int p = 0; p < 2; p++)
#pragma unroll
                    for (int q = 0; q < 10; q++) acc[p][q] = 0ull;
            }
            const float* wrow = s_wh + l * 6400 + (40 * h) * 80 + jb;
            const float* arow = hin + (40 * h) * 128 + col0;
#pragma unroll 2
            for (int kk = 0; kk < 40; kk++) {
                float2 hk = *(const float2*)(arow + kk * 128);
                u64 x0, x1; PACK2(x0, hk.x); PACK2(x1, hk.y);
                FMA_BLOCK(acc, wrow + kk * 80, x0, x1);
            }
            // write partner's j-half
            {
                float* pw = hout + (jb + 10 * oh) * 128 + col0;
#pragma unroll
                for (int qi = 0; qi < 5; qi++) {
                    int q = 5 * oh + qi;
                    float a0, b0, a1, b1;
                    UNPACK2(a0, b0, acc[0][q]); UNPACK2(a1, b1, acc[1][q]);
                    *(float2*)(pw + (2*qi)   * 128) = make_float2(a0, a1);
                    *(float2*)(pw + (2*qi+1) * 128) = make_float2(b0, b1);
                }
            }
            BARW(bid);
            // combine own half + tanh
            {
                float* cw = hout + (jb + 10 * h) * 128 + col0;
#pragma unroll
                for (int qi = 0; qi < 5; qi++) {
                    int q = 5 * h + qi;
                    float2 r0 = *(const float2*)(cw + (2*qi)   * 128);
                    float2 r1 = *(const float2*)(cw + (2*qi+1) * 128);
                    float a0, b0, a1, b1;
                    UNPACK2(a0, b0, acc[0][q]); UNPACK2(a1, b1, acc[1][q]);
                    a0 += r0.x; a1 += r0.y; b0 += r1.x; b1 += r1.y;
                    TANHA(a0, a0); TANHA(a1, a1); TANHA(b0, b0); TANHA(b1, b1);
                    *(float2*)(cw + (2*qi)   * 128) = make_float2(a0, a1);
                    *(float2*)(cw + (2*qi+1) * 128) = make_float2(b0, b1);
                }
            }
            __syncthreads();
            float* tmp = hin; hin = hout; hout = tmp;
        }
        // after 4 swaps: hin == s_A (final hidden), hout == s_B (free)

        // ---- prefetch noise for own strided dims ----
        float nz[3][2];
        {
            int di = 0;
            for (int d = dg; d < 20; d += 8, di++) {
                nz[di][0] = noise[((size_t)step * NTOT + n0) * 22 + d];
                nz[di][1] = noise[((size_t)step * NTOT + n0 + 1) * 22 + d];
            }
        }

        // ======== output layer: group g k in [20jg+10h,+10), 20 j ========
        {
            u64 oc[2][10];
#pragma unroll
            for (int p = 0; p < 2; p++)
#pragma unroll
                for (int q = 0; q < 10; q++) oc[p][q] = 0ull;
            const int kb = 20 * jg + 10 * h;
            const float* hr = hin + kb * 128 + col0;
            const float* wr = s_wout + kb * 20;
#pragma unroll 2
            for (int kk = 0; kk < 10; kk++) {
                float2 hk = *(const float2*)(hr + kk * 128);
                u64 x0, x1; PACK2(x0, hk.x); PACK2(x1, hk.y);
                FMA_BLOCK(oc, wr + kk * 20, x0, x1);
            }
            // pair-combine into s_B rows [20jg, +20) (no activation)
            {
                float* pw = hout + (20 * jg + 10 * oh) * 128 + col0;
#pragma unroll
                for (int qi = 0; qi < 5; qi++) {
                    int q = 5 * oh + qi;
                    float a0, b0, a1, b1;
                    UNPACK2(a0, b0, oc[0][q]); UNPACK2(a1, b1, oc[1][q]);
                    *(float2*)(pw + (2*qi)   * 128) = make_float2(a0, a1);
                    *(float2*)(pw + (2*qi+1) * 128) = make_float2(b0, b1);
                }
            }
            BARW(bid);
            {
                float* cw = hout + (20 * jg + 10 * h) * 128 + col0;
#pragma unroll
                for (int qi = 0; qi < 5; qi++) {
                    int q = 5 * h + qi;
                    float2 r0 = *(const float2*)(cw + (2*qi)   * 128);
                    float2 r1 = *(const float2*)(cw + (2*qi+1) * 128);
                    float a0, b0, a1, b1;
                    UNPACK2(a0, b0, oc[0][q]); UNPACK2(a1, b1, oc[1][q]);
                    a0 += r0.x; a1 += r0.y; b0 += r1.x; b1 += r1.y;
                    *(float2*)(cw + (2*qi)   * 128) = make_float2(a0, a1);
                    *(float2*)(cw + (2*qi+1) * 128) = make_float2(b0, b1);
                }
            }
        }
        __syncthreads();

        // ======== reduce over 4 k-blocks + SDE update (strided dims) =====
        // h = -y ; f = o + y ; uu = 2(o + 2y) ; f_logqp = 2*sum((o+2y)^2)
        {
            float fq0 = 0.f, fq1 = 0.f;
            int di = 0;
            for (int d = dg; d < 20; d += 8, di++) {
                float2 yv = *(const float2*)(s_y + d * 128 + col0);
                float bo = s_bout[d];
                float s0 = bo, s1 = bo;
#pragma unroll
                for (int gb = 0; gb < 4; gb++) {
                    float2 p = *(const float2*)(s_B + (gb * 20 + d) * 128 + col0);
                    s0 += p.x; s1 += p.y;
                }
                float f0 = s0 + yv.x, uu0 = s0 + 2.f * yv.x;
                float f1 = s1 + yv.y, uu1 = s1 + 2.f * yv.y;
                fq0 += uu0 * uu0; fq1 += uu1 * uu1;
                float yn0 = yv.x + f0 * dt + 0.5f * nz[di][0] * sdt; // SIGMA=0.5
                float yn1 = yv.y + f1 * dt + 0.5f * nz[di][1] * sdt;
                *(float2*)(s_y + d * 128 + col0) = make_float2(yn0, yn1);
                ys[((size_t)(step + 1) * NTOT + n0) * 20 + d]       = yn0;
                ys[((size_t)(step + 1) * NTOT + n0 + 1) * 20 + d]   = yn1;
            }
            *(float2*)(s_fq + dg * 128 + col0) = make_float2(fq0, fq1);
        }
        __syncthreads();

        // group 0 (warps 0,1 -> all 64 pairs) owns logqp bookkeeping
        if (g == 0) {
            float f0t = 0.f, f1t = 0.f;
#pragma unroll
            for (int gb = 0; gb < 8; gb++) {
                float2 v = *(const float2*)(s_fq + gb * 128 + col0);
                f0t += v.x; f1t += v.y;
            }
            lq0 += 2.f * f0t * dt;
            lq1 += 2.f * f1t * dt;
            size_t idx0 = (size_t)(step + 1) * NTOT + n0;
            size_t r0 = idx0 - 40;
            if (r0 % 41 == 0) lqout[r0 / 41] = lq0;
            size_t r1 = idx0 + 1 - 40;
            if (r1 % 41 == 0) lqout[r1 / 41] = lq1;
        }
    }
}

// ---------------------------------------------------------------------------
extern "C" void kernel_launch(void* const* d_in, const int* in_sizes, int n_in,
                              void* d_out, int out_size) {
    const float* z      = (const float*)d_in[0];
    const float* t      = (const float*)d_in[1];
    const float* Tx     = (const float*)d_in[2];
    const float* noise  = (const float*)d_in[3];
    const float* tw_in  = (const float*)d_in[4];
    const float* tb_in  = (const float*)d_in[5];
    const float* tw_h   = (const float*)d_in[6];
    const float* tb_h   = (const float*)d_in[7];
    const float* tw_out = (const float*)d_in[8];
    const float* tb_out = (const float*)d_in[9];
    const float* dw_in  = (const float*)d_in[10];
    const float* db_in  = (const float*)d_in[11];
    const float* dw_h   = (const float*)d_in[12];
    const float* db_h   = (const float*)d_in[13];
    const float* dw_out = (const float*)d_in[14];
    const float* db_out = (const float*)d_in[15];

    float* ys    = (float*)d_out;
    float* lqout = ys + (size_t)TLEN * NTOT * 20;

    const size_t smem_bytes = (size_t)SMEM_FLOATS * sizeof(float); // ~215 KB
    cudaFuncSetAttribute(sde_kernel, cudaFuncAttributeMaxDynamicSharedMemorySize,
                         (int)smem_bytes);

    sde_kernel<<<BLOCKS, THREADS, smem_bytes>>>(z, t, Tx, noise,
                                                tw_in, tb_in, tw_h, tb_h,
                                                tw_out, tb_out,
                                                dw_in, db_in, dw_h, db_h,
                                                dw_out, db_out, ys, lqout);
}

// round 12
// speedup vs baseline: 1.5239x; 1.3321x over previous
#include <cuda_runtime.h>
#include <math.h>

#define NTOT    16384
#define TLEN    41
#define NSTEP   40
#define THREADS 256
#define PPB     128          // particles per block; 4 particles per thread
#define BLOCKS  128

// ---- smem float offsets ----
#define OFF_WIN  0            // [24k][80j]
#define OFF_BIN  1920         // [80]
#define OFF_WH   2000         // [4l][80k][80j]
#define OFF_BH   27600        // [4][80]
#define OFF_WOUT 27920        // [80k][20j]
#define OFF_BOUT 29520        // [20]
#define OFF_U    29540        // [40][4]
#define OFF_Y    29700        // [20][128] particle state
#define OFF_FQ   32260        // [8][128] fq partials
#define OFF_A    33284        // [80][128] activations A
#define OFF_B    43524        // [80][128] activations B / output partials
#define SMEM_FLOATS 53764     // 215,056 B

typedef unsigned long long u64;

#define FMA2(d, a, b, c) \
    asm("fma.rn.f32x2 %0, %1, %2, %3;" : "=l"(d) : "l"(a), "l"(b), "l"(c))
#define PACK2(d, f) do { unsigned int _u = __float_as_uint(f); \
    asm("mov.b64 %0, {%1, %2};" : "=l"(d) : "r"(_u), "r"(_u)); } while (0)
#define UNPACK2(lo, hi, s) do { unsigned int _a, _b; \
    asm("mov.b64 {%0, %1}, %2;" : "=r"(_a), "=r"(_b) : "l"(s)); \
    lo = __uint_as_float(_a); hi = __uint_as_float(_b); } while (0)
#define TANHA(d, x) asm("tanh.approx.f32 %0, %1;" : "=f"(d) : "f"(x))

// load 10 consecutive floats (8B-aligned; 16B-aligned when !ODD) into 5 u64
#define LOAD_W10(W, P, ODD)                                                    \
    do {                                                                       \
        const float* _p = (P);                                                 \
        if (ODD) {                                                             \
            W[0] = *(const u64*)_p;                 /* j0,j1  (+0,  8B ok) */  \
            ulonglong2 _a = *(const ulonglong2*)(_p + 2);  /* j2..j5 16B */    \
            ulonglong2 _b = *(const ulonglong2*)(_p + 6);  /* j6..j9 16B */    \
            W[1] = _a.x; W[2] = _a.y; W[3] = _b.x; W[4] = _b.y;                \
        } else {                                                               \
            ulonglong2 _a = *(const ulonglong2*)_p;        /* j0..j3 16B */    \
            ulonglong2 _b = *(const ulonglong2*)(_p + 4);  /* j4..j7 16B */    \
            W[0] = _a.x; W[1] = _a.y; W[2] = _b.x; W[3] = _b.y;                \
            W[4] = *(const u64*)(_p + 8);           /* j8,j9 8B ok */          \
        }                                                                      \
    } while (0)

// 4 particles x 5 packed-j accumulators: 20 FMA2
#define FMA10P4(A, W, X0, X1, X2, X3)                                          \
    do {                                                                       \
        _Pragma("unroll")                                                      \
        for (int _q = 0; _q < 5; _q++) {                                       \
            FMA2(A[0][_q], W[_q], X0, A[0][_q]);                               \
            FMA2(A[1][_q], W[_q], X1, A[1][_q]);                               \
            FMA2(A[2][_q], W[_q], X2, A[2][_q]);                               \
            FMA2(A[3][_q], W[_q], X3, A[3][_q]);                               \
        }                                                                      \
    } while (0)

extern __shared__ float smem[];

__global__ void __launch_bounds__(THREADS, 1)
sde_kernel(const float* __restrict__ z, const float* __restrict__ t,
           const float* __restrict__ Tx, const float* __restrict__ noise,
           const float* __restrict__ tw_in, const float* __restrict__ tb_in,
           const float* __restrict__ tw_h,  const float* __restrict__ tb_h,
           const float* __restrict__ tw_out,const float* __restrict__ tb_out,
           const float* __restrict__ dw_in, const float* __restrict__ db_in,
           const float* __restrict__ dw_h,  const float* __restrict__ db_h,
           const float* __restrict__ dw_out,const float* __restrict__ db_out,
           float* __restrict__ ys, float* __restrict__ lqout) {
    float* s_win  = smem + OFF_WIN;
    float* s_bin  = smem + OFF_BIN;
    float* s_wh   = smem + OFF_WH;
    float* s_bh   = smem + OFF_BH;
    float* s_wout = smem + OFF_WOUT;
    float* s_bout = smem + OFF_BOUT;
    float* s_u    = smem + OFF_U;
    float* s_y    = smem + OFF_Y;
    float* s_fq   = smem + OFF_FQ;
    float* s_A    = smem + OFF_A;
    float* s_B    = smem + OFF_B;

    const int tid  = threadIdx.x;
    const int w    = tid >> 5;      // warp 0..7 == j-group (warp-uniform)
    const int quad = tid & 31;      // particle quad 0..31
    const int col0 = 4 * quad;      // smem column of particle 0 (16B aligned)
    const int jb   = 10 * w;        // MLP j-slice [jb, jb+10)
    const int odd  = w & 1;         // slice byte offset 40w: odd w -> +8 mod 16
    const int jh   = w & 1;         // output-layer j-half
    const int kq   = w >> 1;        // output-layer k-quarter

    // ---- cooperative load + transpose of drift weights into smem ----
    for (int idx = tid; idx < 24 * 80; idx += THREADS) {
        int j = idx / 24, k = idx % 24;
        s_win[k * 80 + j] = dw_in[idx];
    }
    for (int idx = tid; idx < 4 * 6400; idx += THREADS) {
        int l = idx / 6400, r = idx % 6400, j = r / 80, k = r % 80;
        s_wh[l * 6400 + k * 80 + j] = dw_h[idx];
    }
    for (int idx = tid; idx < 20 * 80; idx += THREADS) {
        int j = idx / 80, k = idx % 80;
        s_wout[k * 20 + j] = dw_out[idx];
    }
    for (int idx = tid; idx < 80;  idx += THREADS) s_bin[idx]  = db_in[idx];
    for (int idx = tid; idx < 320; idx += THREADS) s_bh[idx]   = db_h[idx];
    for (int idx = tid; idx < 20;  idx += THREADS) s_bout[idx] = db_out[idx];

    // ---- t-MLP fused: threads [64,104) compute u(t_i) -> s_u ----
    if (tid >= 64 && tid < 64 + NSTEP) {
        int i = tid - 64;
        float ti = t[i];
        float hh[20], h2[20];
#pragma unroll
        for (int j = 0; j < 20; j++) hh[j] = fmaxf(tw_in[j] * ti + tb_in[j], 0.f);
        for (int l = 0; l < 4; l++) {
            const float* ww = tw_h + l * 400;
            const float* bb = tb_h + l * 20;
#pragma unroll
            for (int j = 0; j < 20; j++) {
                float a = bb[j];
#pragma unroll
                for (int k = 0; k < 20; k++) a += ww[j * 20 + k] * hh[k];
                h2[j] = fmaxf(a, 0.f);
            }
#pragma unroll
            for (int j = 0; j < 20; j++) hh[j] = h2[j];
        }
#pragma unroll
        for (int c = 0; c < 4; c++) {
            float a = tb_out[c];
#pragma unroll
            for (int k = 0; k < 20; k++) a += tw_out[c * 20 + k] * hh[k];
            s_u[i * 4 + c] = a;
        }
    }

    const int n0 = blockIdx.x * PPB + col0;   // particles n0..n0+3
    const float Tval = Tx[n0 >> 6];           // same for all 4 (4 | col0)
    const float dt  = t[1] - t[0];
    const float sdt = sqrtf(dt);

    // ---- init: dims strided by warp (d = w, w+8, w+16 when w<4) ----
    for (int d = w; d < 20; d += 8) {
        float v0 = z[(size_t)(n0 + 0) * 20 + d];
        float v1 = z[(size_t)(n0 + 1) * 20 + d];
        float v2 = z[(size_t)(n0 + 2) * 20 + d];
        float v3 = z[(size_t)(n0 + 3) * 20 + d];
        *(float4*)(s_y + d * 128 + col0) = make_float4(v0, v1, v2, v3);
        ys[(size_t)(n0 + 0) * 20 + d] = v0;
        ys[(size_t)(n0 + 1) * 20 + d] = v1;
        ys[(size_t)(n0 + 2) * 20 + d] = v2;
        ys[(size_t)(n0 + 3) * 20 + d] = v3;
    }
    float lq[4] = {0.f, 0.f, 0.f, 0.f};
    if (w == 0) {
#pragma unroll
        for (int p = 0; p < 4; p++) {
            int np = n0 + p;
            if (np >= 40 && (np - 40) % 41 == 0) lqout[(np - 40) / 41] = 0.f;
        }
    }
    __syncthreads();

    for (int step = 0; step < NSTEP; step++) {
        // ======== input layer: [y(20), ut(4)] -> j in [jb, jb+10), relu ===
        {
            u64 acc[4][5];
            {
                u64 Wb[5];
                LOAD_W10(Wb, s_bin + jb, odd);
#pragma unroll
                for (int q = 0; q < 5; q++) {
                    acc[0][q] = Wb[q]; acc[1][q] = Wb[q];
                    acc[2][q] = Wb[q]; acc[3][q] = Wb[q];
                }
            }
#pragma unroll 4
            for (int k = 0; k < 20; k++) {
                float4 yk = *(const float4*)(s_y + k * 128 + col0);
                u64 x0, x1, x2, x3;
                PACK2(x0, yk.x); PACK2(x1, yk.y); PACK2(x2, yk.z); PACK2(x3, yk.w);
                u64 W[5];
                LOAD_W10(W, s_win + k * 80 + jb, odd);
                FMA10P4(acc, W, x0, x1, x2, x3);
            }
#pragma unroll
            for (int c = 0; c < 4; c++) {       // ut identical for 4 particles
                float uv = s_u[step * 4 + c] * Tval;
                u64 xu; PACK2(xu, uv);
                u64 W[5];
                LOAD_W10(W, s_win + (20 + c) * 80 + jb, odd);
                FMA10P4(acc, W, xu, xu, xu, xu);
            }
            float* hw = s_A + jb * 128 + col0;
#pragma unroll
            for (int q = 0; q < 5; q++) {
                float a0,b0,a1,b1,a2,b2,a3,b3;
                UNPACK2(a0,b0,acc[0][q]); UNPACK2(a1,b1,acc[1][q]);
                UNPACK2(a2,b2,acc[2][q]); UNPACK2(a3,b3,acc[3][q]);
                *(float4*)(hw + (2*q)   * 128) =
                    make_float4(fmaxf(a0,0.f), fmaxf(a1,0.f), fmaxf(a2,0.f), fmaxf(a3,0.f));
                *(float4*)(hw + (2*q+1) * 128) =
                    make_float4(fmaxf(b0,0.f), fmaxf(b1,0.f), fmaxf(b2,0.f), fmaxf(b3,0.f));
            }
        }
        __syncthreads();

        // ======== 4 hidden layers 80 -> 80, tanh.approx ========
        float* hin  = s_A;
        float* hout = s_B;
        for (int l = 0; l < 4; l++) {
            u64 acc[4][5];
            {
                u64 Wb[5];
                LOAD_W10(Wb, s_bh + l * 80 + jb, odd);
#pragma unroll
                for (int q = 0; q < 5; q++) {
                    acc[0][q] = Wb[q]; acc[1][q] = Wb[q];
                    acc[2][q] = Wb[q]; acc[3][q] = Wb[q];
                }
            }
            const float* wl = s_wh + l * 6400 + jb;
#pragma unroll 4
            for (int k = 0; k < 80; k++) {
                float4 hk = *(const float4*)(hin + k * 128 + col0);
                u64 x0, x1, x2, x3;
                PACK2(x0, hk.x); PACK2(x1, hk.y); PACK2(x2, hk.z); PACK2(x3, hk.w);
                u64 W[5];
                LOAD_W10(W, wl + k * 80, odd);
                FMA10P4(acc, W, x0, x1, x2, x3);
            }
            float* hw = hout + jb * 128 + col0;
#pragma unroll
            for (int q = 0; q < 5; q++) {
                float a0,b0,a1,b1,a2,b2,a3,b3;
                UNPACK2(a0,b0,acc[0][q]); UNPACK2(a1,b1,acc[1][q]);
                UNPACK2(a2,b2,acc[2][q]); UNPACK2(a3,b3,acc[3][q]);
                TANHA(a0,a0); TANHA(a1,a1); TANHA(a2,a2); TANHA(a3,a3);
                TANHA(b0,b0); TANHA(b1,b1); TANHA(b2,b2); TANHA(b3,b3);
                *(float4*)(hw + (2*q)   * 128) = make_float4(a0,a1,a2,a3);
                *(float4*)(hw + (2*q+1) * 128) = make_float4(b0,b1,b2,b3);
            }
            __syncthreads();
            float* tmp = hin; hin = hout; hout = tmp;
        }
        // after 4 swaps: hin == s_A (final hidden), hout == s_B (free)

        // ---- prefetch noise for own strided dims (hidden under output) ---
        float nz[3][4];
        {
            int di = 0;
            for (int d = w; d < 20; d += 8, di++) {
#pragma unroll
                for (int p = 0; p < 4; p++)
                    nz[di][p] = noise[((size_t)step * NTOT + n0 + p) * 22 + d];
            }
        }

        // ======== output layer: k in [20kq,+20), j in [10jh,+10) ==========
        // (bias added once in the reduce phase; partials zero-init here)
        {
            u64 oc[4][5];
#pragma unroll
            for (int q = 0; q < 5; q++) {
                oc[0][q] = 0ull; oc[1][q] = 0ull; oc[2][q] = 0ull; oc[3][q] = 0ull;
            }
            const float* hr = hin + (20 * kq) * 128 + col0;
            const float* wr = s_wout + (20 * kq) * 20 + 10 * jh;
#pragma unroll 4
            for (int kk = 0; kk < 20; kk++) {
                float4 hk = *(const float4*)(hr + kk * 128);
                u64 x0, x1, x2, x3;
                PACK2(x0, hk.x); PACK2(x1, hk.y); PACK2(x2, hk.z); PACK2(x3, hk.w);
                u64 W[5];
                LOAD_W10(W, wr + kk * 20, jh);
                FMA10P4(oc, W, x0, x1, x2, x3);
            }
            // partial rows = 20*kq + 10*jh + jj  (80 rows total in s_B)
            float* pw = s_B + (20 * kq + 10 * jh) * 128 + col0;
#pragma unroll
            for (int q = 0; q < 5; q++) {
                float a0,b0,a1,b1,a2,b2,a3,b3;
                UNPACK2(a0,b0,oc[0][q]); UNPACK2(a1,b1,oc[1][q]);
                UNPACK2(a2,b2,oc[2][q]); UNPACK2(a3,b3,oc[3][q]);
                *(float4*)(pw + (2*q)   * 128) = make_float4(a0,a1,a2,a3);
                *(float4*)(pw + (2*q+1) * 128) = make_float4(b0,b1,b2,b3);
            }
        }
        __syncthreads();

        // ======== reduce over 4 k-quarters + SDE update (strided dims) ====
        // h = -y ; f = o + y ; uu = 2(o + 2y) ; f_logqp = 2*sum((o+2y)^2)
        {
            float fq[4] = {0.f, 0.f, 0.f, 0.f};
            int di = 0;
            for (int d = w; d < 20; d += 8, di++) {
                float4 yv = *(const float4*)(s_y + d * 128 + col0);
                float bo = s_bout[d];
                float s0 = bo, s1 = bo, s2 = bo, s3 = bo;
#pragma unroll
                for (int g = 0; g < 4; g++) {
                    float4 p = *(const float4*)(s_B + (g * 20 + d) * 128 + col0);
                    s0 += p.x; s1 += p.y; s2 += p.z; s3 += p.w;
                }
                float yv_[4] = {yv.x, yv.y, yv.z, yv.w};
                float sv[4]  = {s0, s1, s2, s3};
                float yn[4];
#pragma unroll
                for (int p = 0; p < 4; p++) {
                    float f  = sv[p] + yv_[p];
                    float uu = sv[p] + 2.f * yv_[p];
                    fq[p] += uu * uu;
                    yn[p] = yv_[p] + f * dt + 0.5f * nz[di][p] * sdt; // SIGMA=0.5
                    ys[((size_t)(step + 1) * NTOT + n0 + p) * 20 + d] = yn[p];
                }
                *(float4*)(s_y + d * 128 + col0) =
                    make_float4(yn[0], yn[1], yn[2], yn[3]);
            }
            *(float4*)(s_fq + w * 128 + col0) =
                make_float4(fq[0], fq[1], fq[2], fq[3]);
        }
        __syncthreads();

        // warp 0 owns logqp bookkeeping (s_fq stable until next step's update)
        if (w == 0) {
            float ft[4] = {0.f, 0.f, 0.f, 0.f};
#pragma unroll
            for (int g = 0; g < 8; g++) {
                float4 v = *(const float4*)(s_fq + g * 128 + col0);
                ft[0] += v.x; ft[1] += v.y; ft[2] += v.z; ft[3] += v.w;
            }
#pragma unroll
            for (int p = 0; p < 4; p++) {
                lq[p] += 2.f * ft[p] * dt;
                size_t idx = (size_t)(step + 1) * NTOT + n0 + p;
                size_t r = idx - 40;
                if (r % 41 == 0) lqout[r / 41] = lq[p];
            }
        }
    }
}

// ---------------------------------------------------------------------------
extern "C" void kernel_launch(void* const* d_in, const int* in_sizes, int n_in,
                              void* d_out, int out_size) {
    const float* z      = (const float*)d_in[0];
    const float* t      = (const float*)d_in[1];
    const float* Tx     = (const float*)d_in[2];
    const float* noise  = (const float*)d_in[3];
    const float* tw_in  = (const float*)d_in[4];
    const float* tb_in  = (const float*)d_in[5];
    const float* tw_h   = (const float*)d_in[6];
    const float* tb_h   = (const float*)d_in[7];
    const float* tw_out = (const float*)d_in[8];
    const float* tb_out = (const float*)d_in[9];
    const float* dw_in  = (const float*)d_in[10];
    const float* db_in  = (const float*)d_in[11];
    const float* dw_h   = (const float*)d_in[12];
    const float* db_h   = (const float*)d_in[13];
    const float* dw_out = (const float*)d_in[14];
    const float* db_out = (const float*)d_in[15];

    float* ys    = (float*)d_out;
    float* lqout = ys + (size_t)TLEN * NTOT * 20;

    const size_t smem_bytes = (size_t)SMEM_FLOATS * sizeof(float); // ~215 KB
    cudaFuncSetAttribute(sde_kernel, cudaFuncAttributeMaxDynamicSharedMemorySize,
                         (int)smem_bytes);

    sde_kernel<<<BLOCKS, THREADS, smem_bytes>>>(z, t, Tx, noise,
                                                tw_in, tb_in, tw_h, tb_h,
                                                tw_out, tb_out,
                                                dw_in, db_in, dw_h, db_h,
                                                dw_out, db_out, ys, lqout);
}